// round 16
// baseline (speedup 1.0000x reference)
#include <cuda_runtime.h>
#include <cuda_fp16.h>
#include <math.h>

#define Bn 1024
#define Ln 64
#define Hn 512
#define NCTA 256
#define NTHREADS 256

// Single-assignment e4m3 state in A-fragment order:
//   g_S8[layer][u][mb(64)][k32(16)][512B], u = t+1 (u=0 is the zero initial state)
__device__ __align__(16) unsigned char g_S8[4][Ln + 1][64][16][512];   // 130 MB
// weights in B-fragment order: [layer7][n8(64)][k32(16)][lane(32)][8B]
__device__ __align__(16) unsigned char g_W8[7 * 64 * 16 * 32 * 8];     // 1.75 MB
__device__ __half g_h16[Ln][Bn][Hn];     // 64 MB layer-3 outputs (linear, logp path)
__device__ float  g_lp[8][Bn];           // per-t-chunk partial log-probs
__device__ int    g_done[4][Ln + 1][8];  // ready counters: D[j][u][mi] == 8 -> slab ready
__device__ unsigned g_count;
__device__ volatile unsigned g_gen;

// ---------------------------------------------------------------------------
__device__ __forceinline__ void mma_f8(float c[4], const uint4 a,
                                       unsigned b0, unsigned b1) {
    asm volatile(
        "mma.sync.aligned.m16n8k32.row.col.f32.e4m3.e4m3.f32 "
        "{%0,%1,%2,%3}, {%4,%5,%6,%7}, {%8,%9}, {%0,%1,%2,%3};"
        : "+f"(c[0]), "+f"(c[1]), "+f"(c[2]), "+f"(c[3])
        : "r"(a.x), "r"(a.y), "r"(a.z), "r"(a.w), "r"(b0), "r"(b1));
}
__device__ __forceinline__ unsigned short pk2(float lo, float hi) {
    unsigned short r;
    asm("cvt.rn.satfinite.e4m3x2.f32 %0, %1, %2;" : "=h"(r) : "f"(hi), "f"(lo));
    return r;
}
__device__ __forceinline__ unsigned pk4(float b0, float b1, float b2, float b3) {
    return (unsigned)pk2(b0, b1) | ((unsigned)pk2(b2, b3) << 16);
}

// One-shot global barrier (prologue only).
__device__ __forceinline__ void gbar(unsigned target) {
    __syncthreads();
    if (threadIdx.x == 0) {
        __threadfence();
        unsigned t = atomicAdd(&g_count, 1);
        if (t == NCTA - 1) {
            atomicExch(&g_count, 0);
            __threadfence();
            g_gen = target;
        } else {
            while ((int)(g_gen - target) < 0) {}
            __threadfence();
        }
    }
    __syncthreads();
}

// One 128x64 job (R15-verbatim compute, bit-identical numerics).
template <bool DUAL, bool LAYER0, bool STORE>
__device__ __forceinline__ void do_job(
    int t,
    const uint4* __restrict__ A1f, const uint4* __restrict__ A2f,
    int l1, int l2,
    const float* __restrict__ bias, const int* __restrict__ x,
    const float* __restrict__ Win0,
    unsigned char* __restrict__ Cout,
    int m0, int n0)
{
    const int tid  = threadIdx.x;
    const int warp = tid >> 5, lane = tid & 31;
    const int mw = warp >> 1;
    const int nw = warp & 1;
    const int quad = lane >> 2, qt = lane & 3;
    const int n8b = (n0 >> 3) + nw * 4;
    const int mb0 = (m0 >> 4) + mw * 2;

    const uint2* Wf = reinterpret_cast<const uint2*>(g_W8);

    float acc[2][4][4];
#pragma unroll
    for (int a = 0; a < 2; a++)
#pragma unroll
        for (int b = 0; b < 4; b++)
#pragma unroll
            for (int v = 0; v < 4; v++) acc[a][b][v] = 0.f;

    const int NKG = DUAL ? 32 : 16;
#pragma unroll 8
    for (int kg = 0; kg < NKG; kg++) {
        const bool ph = DUAL && (kg >= 16);
        const uint4* Af = ph ? A2f : A1f;
        const int lsel = ph ? l2 : l1;
        const int kk = kg & 15;

        const uint4 a0 = Af[((mb0 + 0) * 16 + kk) * 32 + lane];
        const uint4 a1 = Af[((mb0 + 1) * 16 + kk) * 32 + lane];
        uint2 bv[4];
#pragma unroll
        for (int nb = 0; nb < 4; nb++)
            bv[nb] = Wf[(((lsel * 64) + n8b + nb) * 16 + kk) * 32 + lane];

#pragma unroll
        for (int nb = 0; nb < 4; nb++) {
            mma_f8(acc[0][nb], a0, bv[nb].x, bv[nb].y);
            mma_f8(acc[1][nb], a1, bv[nb].x, bv[nb].y);
        }
    }

    // epilogue: + bias (+ Win0[x[t-1]] row for layer 0), ELU, fragment store
#pragma unroll
    for (int ma = 0; ma < 2; ma++) {
        const int r0 = m0 + mw * 32 + ma * 16 + quad;
        const int mb = mb0 + ma;
        int idx0 = 0, idx1 = 0;
        const bool l0add = LAYER0 && (t > 0);
        if (l0add) {
            idx0 = x[r0 * Ln + (t - 1)];
            idx1 = x[(r0 + 8) * Ln + (t - 1)];
        }
#pragma unroll
        for (int nb = 0; nb < 4; nb++) {
            const int col = n0 + nw * 32 + nb * 8 + 2 * qt;
            const float2 bv = *reinterpret_cast<const float2*>(&bias[col]);
            float2 w0 = make_float2(0.f, 0.f), w1 = make_float2(0.f, 0.f);
            if (l0add) {
                w0 = *reinterpret_cast<const float2*>(&Win0[idx0 * Hn + col]);
                w1 = *reinterpret_cast<const float2*>(&Win0[idx1 * Hn + col]);
            }
            float v0 = acc[ma][nb][0] + bv.x + w0.x;
            float v1 = acc[ma][nb][1] + bv.y + w0.y;
            float v2 = acc[ma][nb][2] + bv.x + w1.x;
            float v3 = acc[ma][nb][3] + bv.y + w1.y;
            v0 = (v0 > 0.f) ? v0 : expm1f(v0);
            v1 = (v1 > 0.f) ? v1 : expm1f(v1);
            v2 = (v2 > 0.f) ? v2 : expm1f(v2);
            v3 = (v3 > 0.f) ? v3 : expm1f(v3);

            const int k32   = col >> 5;
            const int lanep = quad * 4 + ((col >> 2) & 3);
            const int bhi   = ((col >> 4) & 1) * 8 + (col & 3);
            unsigned char* fb = Cout + ((mb * 16 + k32) * 32 + lanep) * 16 + bhi;
            *reinterpret_cast<unsigned short*>(fb)     = pk2(v0, v1);
            *reinterpret_cast<unsigned short*>(fb + 4) = pk2(v2, v3);
            if (STORE) {
                *reinterpret_cast<__half2*>(&g_h16[t][r0][col])     = __floats2half2_rn(v0, v1);
                *reinterpret_cast<__half2*>(&g_h16[t][r0 + 8][col]) = __floats2half2_rn(v2, v3);
            }
        }
    }
}

// ---------------------------------------------------------------------------
__global__ void __launch_bounds__(NTHREADS, 2) rnn_persistent(
    const int*   __restrict__ x,         // [B][L]
    const float* __restrict__ Win0,      // [2][H]
    const float* __restrict__ Win_rest,  // [3][H][H]
    const float* __restrict__ Wc,        // [4][H][H]
    const float* __restrict__ bc)        // [4][H]
{
    const int tid  = threadIdx.x;
    const int cta  = blockIdx.x;
    const int gtid = cta * NTHREADS + tid;

    unsigned base = g_gen;
    unsigned bar  = 0;

    // --- prologue: pack weights; zero u=0 slabs; init dependency flags ------
    {
        unsigned* W32 = reinterpret_cast<unsigned*>(g_W8);
        const int NW = 7 * 64 * 16 * 32 * 2;
        for (int w = gtid; w < NW; w += NCTA * NTHREADS) {
            const int reg  = w & 1;
            const int lane = (w >> 1) & 31;
            const int kc   = (w >> 6) & 15;
            const int n8   = (w >> 10) & 63;
            const int l    = w >> 16;
            const int k = kc * 32 + (lane & 3) * 4 + reg * 16;
            const int n = n8 * 8 + (lane >> 2);
            const float* Wsrc = (l < 4) ? (Wc + l * Hn * Hn)
                                        : (Win_rest + (l - 4) * Hn * Hn);
            const float f0 = Wsrc[(k + 0) * Hn + n];
            const float f1 = Wsrc[(k + 1) * Hn + n];
            const float f2 = Wsrc[(k + 2) * Hn + n];
            const float f3 = Wsrc[(k + 3) * Hn + n];
            W32[w] = pk4(f0, f1, f2, f3);
        }
        // zero the u=0 (initial) state slabs: 4 x 512KB
        const uint4 z4 = make_uint4(0u, 0u, 0u, 0u);
        for (int i = gtid; i < 4 * 64 * 16 * 512 / 16; i += NCTA * NTHREADS) {
            const int jj = i / (64 * 16 * 32);
            const int r  = i % (64 * 16 * 32);
            reinterpret_cast<uint4*>(&g_S8[jj][0][0][0][0])[r] = z4;
        }
        // init flags: D[j][0][mi] = 8 (initial state ready); others 0
        for (int i = gtid; i < 4 * (Ln + 1) * 8; i += NCTA * NTHREADS) {
            const int u = (i >> 3) % (Ln + 1);
            (&g_done[0][0][0])[i] = (u == 0) ? 8 : 0;
        }
    }
    gbar(base + (++bar));   // one-time rendezvous: prologue visible everywhere

    // --- dataflow main loop: CTA pinned to (layer j, m-slice, n-slice) ------
    const int j    = cta >> 6;             // 0..3
    const int tile = cta & 63;
    const int mi   = tile >> 3;            // 8 m-slices of 128 rows
    const int m0   = mi * 128;
    const int n0   = (tile & 7) * 64;

    const int l1 = j;
    const int l2 = (j > 0) ? (4 + j - 1) : j;
    const float* bias = bc + j * Hn;

    for (int t = 0; t < Ln; t++) {
        // wait for inputs: own S[j][t] slab + (j>0) S[j-1][t+1] slab
        if (tid == 0) {
            volatile int* d1 = &g_done[j][t][mi];
            while (*d1 < 8) {}
            if (j > 0) {
                volatile int* d2 = &g_done[j - 1][t + 1][mi];
                while (*d2 < 8) {}
            }
        }
        __syncthreads();

        const uint4* A1f = reinterpret_cast<const uint4*>(&g_S8[j][t][0][0][0]);
        const uint4* A2f = (j > 0)
            ? reinterpret_cast<const uint4*>(&g_S8[j - 1][t + 1][0][0][0]) : A1f;
        unsigned char* Cout = &g_S8[j][t + 1][0][0][0];

        switch (j) {
            case 0:
                do_job<false, true, false>(t, A1f, A2f, l1, l2, bias, x, Win0, Cout, m0, n0);
                break;
            case 3:
                do_job<true, false, true>(t, A1f, A2f, l1, l2, bias, x, Win0, Cout, m0, n0);
                break;
            default:
                do_job<true, false, false>(t, A1f, A2f, l1, l2, bias, x, Win0, Cout, m0, n0);
                break;
        }

        // publish: all stores -> L2, then arrive on this slab's counter
        __threadfence();
        __syncthreads();
        if (tid == 0)
            atomicAdd(&g_done[j][t + 1][mi], 1);
    }
}

// ---------------------------------------------------------------------------
// Log-prob partials: warp (b, tc) handles 8 timesteps, writes g_lp[tc][b].
// ---------------------------------------------------------------------------
__global__ void logp_part(const float* __restrict__ Wout,  // [H][2]
                          const float* __restrict__ bout,  // [2]
                          const int*   __restrict__ xsym)  // [B][L]
{
    const int gw   = (blockIdx.x * blockDim.x + threadIdx.x) >> 5;
    const int lane = threadIdx.x & 31;
    const int b  = gw >> 3;
    const int tc = gw & 7;
    if (b >= Bn) return;

    float w0[16], w1[16];
#pragma unroll
    for (int i = 0; i < 8; i++) {
        const int k = lane * 2 + 64 * i;
        w0[2 * i]     = Wout[k * 2 + 0];
        w1[2 * i]     = Wout[k * 2 + 1];
        w0[2 * i + 1] = Wout[(k + 1) * 2 + 0];
        w1[2 * i + 1] = Wout[(k + 1) * 2 + 1];
    }
    const float b0 = bout[0], b1 = bout[1];

    float acc = 0.f;
#pragma unroll
    for (int tt = 0; tt < 8; tt++) {
        const int t = tc * 8 + tt;
        const __half* h = &g_h16[t][b][0];
        float s0 = 0.f, s1 = 0.f;
#pragma unroll
        for (int i = 0; i < 8; i++) {
            const __half2 hv = *reinterpret_cast<const __half2*>(&h[lane * 2 + 64 * i]);
            const float h0 = __half2float(hv.x);
            const float h1 = __half2float(hv.y);
            s0 += h0 * w0[2 * i] + h1 * w0[2 * i + 1];
            s1 += h0 * w1[2 * i] + h1 * w1[2 * i + 1];
        }
#pragma unroll
        for (int off = 16; off > 0; off >>= 1) {
            s0 += __shfl_xor_sync(0xffffffffu, s0, off);
            s1 += __shfl_xor_sync(0xffffffffu, s1, off);
        }
        s0 += b0; s1 += b1;
        const float m   = fmaxf(s0, s1);
        const float lse = m + logf(expf(s0 - m) + expf(s1 - m));
        const float sel = (xsym[b * Ln + t] == 0) ? s0 : s1;
        acc += sel - lse;
    }
    if (lane == 0) g_lp[tc][b] = acc;
}

// Deterministic final sum: out[b] = 0.5 * sum_tc g_lp[tc][b]
__global__ void logp_sum(float* __restrict__ out) {
    const int b = blockIdx.x * blockDim.x + threadIdx.x;
    if (b >= Bn) return;
    float s = 0.f;
#pragma unroll
    for (int tc = 0; tc < 8; tc++) s += g_lp[tc][b];
    out[b] = 0.5f * s;
}

// ---------------------------------------------------------------------------
extern "C" void kernel_launch(void* const* d_in, const int* in_sizes, int n_in,
                              void* d_out, int out_size) {
    (void)in_sizes; (void)n_in; (void)out_size;
    const int*   x        = (const int*)  d_in[0];  // [B, L]
    const float* Win0     = (const float*)d_in[1];  // [2, H]
    const float* Win_rest = (const float*)d_in[2];  // [3, H, H]
    const float* Wc       = (const float*)d_in[3];  // [4, H, H]
    const float* bc       = (const float*)d_in[4];  // [4, H]
    const float* Wout     = (const float*)d_in[5];  // [H, 2]
    const float* bout     = (const float*)d_in[6];  // [2]
    float* out = (float*)d_out;                     // [B]

    rnn_persistent<<<NCTA, NTHREADS>>>(x, Win0, Win_rest, Wc, bc);
    logp_part<<<(Bn * 8) / 8, 256>>>(Wout, bout, x);   // 1024 blocks, 8 warps each
    logp_sum<<<Bn / 256, 256>>>(out);
}